// round 16
// baseline (speedup 1.0000x reference)
#include <cuda_runtime.h>
#include <cstdint>

#define B_ 4
#define C_ 64
#define N_ 100000
#define K_ 6
#define BN_ (B_ * N_)
#define EPS_ 1e-5f
#define TILE_V 128
#define NTILES ((N_ + TILE_V - 1) / TILE_V)   // 782
#define GSTRIDE 132                           // padded G row stride (floats)
#define SMEM_BYTES (32768 + 128 * GSTRIDE * 4)  // Ws 32KB + G 66KB = 100352

// device scratch
__device__ float g_xt[(size_t)BN_ * 64];   // x transposed [B*N][64]
__device__ float g_h[(size_t)BN_ * 64];    // conv1 pre-relu output
__device__ float g_W0t[128 * 64];          // W as [k(=s*64+c)][o]
__device__ float g_W1t[128 * 64];
__device__ float g_sum[64], g_ssq[64], g_a[64], g_bc[64];

__device__ __forceinline__ void ffma2(unsigned long long& d,
                                      unsigned long long a,
                                      unsigned long long b) {
    asm("fma.rn.f32x2 %0, %1, %2, %0;" : "+l"(d) : "l"(a), "l"(b));
}
__device__ __forceinline__ unsigned long long dup2(float g) {
    unsigned long long v;
    asm("mov.b64 %0, {%1, %1};" : "=l"(v) : "f"(g));
    return v;
}
__device__ __forceinline__ float2 u2f(unsigned long long v) {
    float2 f; asm("mov.b64 {%0,%1}, %2;" : "=f"(f.x), "=f"(f.y) : "l"(v)); return f;
}

// ---------------------------------------------------------------------------
__global__ void prep_k(const float* __restrict__ W0, const float* __restrict__ W1) {
    int t = threadIdx.x;
    if (t < 64) { g_sum[t] = 0.f; g_ssq[t] = 0.f; }
    for (int d = t; d < 8192; d += 256) {
        int k = d >> 6, o = d & 63;
        int c = k & 63, s = k >> 6;
        int src = o * 128 + c * 2 + s;
        g_W0t[d] = W0[src];
        g_W1t[d] = W1[src];
    }
}

__global__ void dummy_k() {}

// ---------------------------------------------------------------------------
__global__ void transpose_k(const float* __restrict__ x) {
    __shared__ float tile[64][33];
    int b = blockIdx.y;
    int n0 = blockIdx.x * 32;
    const float* xb = x + (size_t)b * C_ * N_;
    int t = threadIdx.x;
#pragma unroll
    for (int i = 0; i < 8; i++) {
        int idx = t + i * 256;
        int c = idx >> 5, j = idx & 31;
        tile[c][j] = xb[(size_t)c * N_ + n0 + j];
    }
    __syncthreads();
    float* dst = g_xt + ((size_t)b * N_ + n0) * C_;
#pragma unroll
    for (int i = 0; i < 8; i++) {
        int idx = t + i * 256;
        int j = idx >> 6, c = idx & 63;
        dst[j * C_ + c] = tile[c][j];
    }
}

// ---------------------------------------------------------------------------
// GEMM: G [128 k][GSTRIDE], Ws [128 k][64 o]; thread = 4 consecutive vertices
// (vg) x 8 outputs (og). Per warp-k: G = 4 addrs broadcast (1 wf), W = 2x
// 128B-span (1 wf each).
// ---------------------------------------------------------------------------
__device__ __forceinline__ void gemm_core(const float* __restrict__ G,
                                          const float* __restrict__ Ws,
                                          int vg, int og, float av[4][8]) {
    unsigned long long acc[4][4];
#pragma unroll
    for (int v = 0; v < 4; v++)
#pragma unroll
        for (int p = 0; p < 4; p++) acc[v][p] = 0ull;

    const float* Gp = G + 4 * vg;
    const float* Wp = Ws + og * 8;
#pragma unroll 16
    for (int k = 0; k < 128; k++) {
        float4 g4 = *(const float4*)(Gp + (size_t)k * GSTRIDE);
        ulonglong2 w01 = *(const ulonglong2*)(Wp + (size_t)k * 64);
        ulonglong2 w23 = *(const ulonglong2*)(Wp + (size_t)k * 64 + 4);
        unsigned long long gd0 = dup2(g4.x), gd1 = dup2(g4.y);
        unsigned long long gd2 = dup2(g4.z), gd3 = dup2(g4.w);
        ffma2(acc[0][0], gd0, w01.x); ffma2(acc[0][1], gd0, w01.y);
        ffma2(acc[0][2], gd0, w23.x); ffma2(acc[0][3], gd0, w23.y);
        ffma2(acc[1][0], gd1, w01.x); ffma2(acc[1][1], gd1, w01.y);
        ffma2(acc[1][2], gd1, w23.x); ffma2(acc[1][3], gd1, w23.y);
        ffma2(acc[2][0], gd2, w01.x); ffma2(acc[2][1], gd2, w01.y);
        ffma2(acc[2][2], gd2, w23.x); ffma2(acc[2][3], gd2, w23.y);
        ffma2(acc[3][0], gd3, w01.x); ffma2(acc[3][1], gd3, w01.y);
        ffma2(acc[3][2], gd3, w23.x); ffma2(acc[3][3], gd3, w23.y);
    }
#pragma unroll
    for (int v = 0; v < 4; v++)
#pragma unroll
        for (int p = 0; p < 4; p++) {
            float2 f = u2f(acc[v][p]);
            av[v][2 * p] = f.x;
            av[v][2 * p + 1] = f.y;
        }
}

// ---------------------------------------------------------------------------
// conv1: coalesced gather (4 lanes/vertex, 2 passes) -> padded G; GEMM with
// og=tid&7 mapping; store h; relu stats.
// ---------------------------------------------------------------------------
__global__ __launch_bounds__(256, 2) void conv1_k(const int* __restrict__ neigh) {
    extern __shared__ float smem[];
    float* Ws = smem;            // [128][64] 32 KB
    float* G  = smem + 8192;     // [128][GSTRIDE]

    int tid = threadIdx.x;
    int b = blockIdx.y, n0 = blockIdx.x * TILE_V, rbase = b * N_;

    {   // stage weights
        const float4* src = (const float4*)g_W0t;
        float4* dst = (float4*)Ws;
        for (int i = tid; i < 2048; i += 256) dst[i] = src[i];
    }

    {   // gather: lane = (vs = tid>>2, q = tid&3); 2 passes of 64 vertices.
        int q = tid & 3, vs = tid >> 2;
        const float4* xt4 = (const float4*)g_xt;
#pragma unroll
        for (int p = 0; p < 2; p++) {
            int v = p * 64 + vs;
            int n = n0 + v;
            bool ok = (n < N_);
            float4 cen[4], sm[4];
#pragma unroll
            for (int m = 0; m < 4; m++) {
                cen[m] = make_float4(0.f, 0.f, 0.f, 0.f);
                sm[m]  = make_float4(0.f, 0.f, 0.f, 0.f);
            }
            if (ok) {
                size_t vr = (size_t)(rbase + n) * 16 + q;
#pragma unroll
                for (int m = 0; m < 4; m++) cen[m] = xt4[vr + 4 * m];
                const int* nb = neigh + (size_t)(rbase + n) * K_;
                int idx[6] = {nb[0], nb[1], nb[2], nb[3], nb[4], nb[5]};
#pragma unroll
                for (int k = 0; k < 6; k++) {
                    size_t r = (size_t)(rbase + idx[k]) * 16 + q;
#pragma unroll
                    for (int m = 0; m < 4; m++) {
                        float4 a = xt4[r + 4 * m];
                        sm[m].x += a.x; sm[m].y += a.y; sm[m].z += a.z; sm[m].w += a.w;
                    }
                }
            }
#pragma unroll
            for (int m = 0; m < 4; m++) {
                int c0 = 4 * (q + 4 * m);
                G[(c0 + 0) * GSTRIDE + v] = cen[m].x;
                G[(c0 + 1) * GSTRIDE + v] = cen[m].y;
                G[(c0 + 2) * GSTRIDE + v] = cen[m].z;
                G[(c0 + 3) * GSTRIDE + v] = cen[m].w;
                G[(64 + c0 + 0) * GSTRIDE + v] = sm[m].x;
                G[(64 + c0 + 1) * GSTRIDE + v] = sm[m].y;
                G[(64 + c0 + 2) * GSTRIDE + v] = sm[m].z;
                G[(64 + c0 + 3) * GSTRIDE + v] = sm[m].w;
            }
        }
    }
    __syncthreads();

    int og = tid & 7, vg = tid >> 3;    // NEW mapping: 4 consecutive vertices
    float av[4][8];
    gemm_core(G, Ws, vg, og, av);

    // h store: per instr, 8 og lanes x 4 vertices -> 256B-contiguous runs
    float4* h4 = (float4*)g_h;
#pragma unroll
    for (int i = 0; i < 4; i++) {
        int n = n0 + 4 * vg + i;
        if (n < N_) {
            size_t row = (size_t)(rbase + n) * 16 + og * 2;
            h4[row]     = make_float4(av[i][0], av[i][1], av[i][2], av[i][3]);
            h4[row + 1] = make_float4(av[i][4], av[i][5], av[i][6], av[i][7]);
        }
    }

    // relu stats: lanes l, l^8, l^16, l^24 share og -> reduce, lanes 0-7 emit
#pragma unroll
    for (int o = 0; o < 8; o++) {
        float s = 0.f, q2 = 0.f;
#pragma unroll
        for (int i = 0; i < 4; i++) {
            float r = fmaxf(av[i][o], 0.f);
            s += r; q2 += r * r;
        }
        s  += __shfl_xor_sync(0xffffffffu, s, 8);
        q2 += __shfl_xor_sync(0xffffffffu, q2, 8);
        s  += __shfl_xor_sync(0xffffffffu, s, 16);
        q2 += __shfl_xor_sync(0xffffffffu, q2, 16);
        if ((tid & 31) < 8) {
            atomicAdd(&g_sum[og * 8 + o], s);
            atomicAdd(&g_ssq[og * 8 + o], q2);
        }
    }
}

// ---------------------------------------------------------------------------
__global__ void finalize_k(const float* __restrict__ gamma, const float* __restrict__ beta) {
    int c = threadIdx.x;
    float inv = 1.f / (float)BN_;
    float mean = g_sum[c] * inv;
    float var = g_ssq[c] * inv - mean * mean;
    float a = gamma[c] * rsqrtf(var + EPS_);
    g_a[c] = a;
    g_bc[c] = beta[c] - mean * a;
}

// ---------------------------------------------------------------------------
// conv2: coalesced gather with BN-affine fold; GEMM (new mapping); +residual;
// relu; transposed output stores.
// ---------------------------------------------------------------------------
__global__ __launch_bounds__(256, 2) void conv2_k(const int* __restrict__ neigh,
                                                  float* __restrict__ out) {
    extern __shared__ float smem[];
    float* Ws = smem;
    float* G  = smem + 8192;

    int tid = threadIdx.x;
    int b = blockIdx.y, n0 = blockIdx.x * TILE_V, rbase = b * N_;

    {
        const float4* src = (const float4*)g_W1t;
        float4* dst = (float4*)Ws;
        for (int i = tid; i < 2048; i += 256) dst[i] = src[i];
    }

    {   // gather: center a*relu(h)+b ; neighbors a*sum(relu(h_k)) + 6b
        int q = tid & 3, vs = tid >> 2;
        const float4* h4 = (const float4*)g_h;
#pragma unroll
        for (int p = 0; p < 2; p++) {
            int v = p * 64 + vs;
            int n = n0 + v;
            bool ok = (n < N_);
            float4 cen[4], sm[4];
#pragma unroll
            for (int m = 0; m < 4; m++) {
                cen[m] = make_float4(0.f, 0.f, 0.f, 0.f);
                sm[m]  = make_float4(0.f, 0.f, 0.f, 0.f);
            }
            if (ok) {
                size_t vr = (size_t)(rbase + n) * 16 + q;
#pragma unroll
                for (int m = 0; m < 4; m++) {
                    float4 hv = h4[vr + 4 * m];
                    cen[m].x = fmaxf(hv.x, 0.f);
                    cen[m].y = fmaxf(hv.y, 0.f);
                    cen[m].z = fmaxf(hv.z, 0.f);
                    cen[m].w = fmaxf(hv.w, 0.f);
                }
                const int* nb = neigh + (size_t)(rbase + n) * K_;
                int idx[6] = {nb[0], nb[1], nb[2], nb[3], nb[4], nb[5]};
#pragma unroll
                for (int k = 0; k < 6; k++) {
                    size_t r = (size_t)(rbase + idx[k]) * 16 + q;
#pragma unroll
                    for (int m = 0; m < 4; m++) {
                        float4 a = h4[r + 4 * m];
                        sm[m].x += fmaxf(a.x, 0.f); sm[m].y += fmaxf(a.y, 0.f);
                        sm[m].z += fmaxf(a.z, 0.f); sm[m].w += fmaxf(a.w, 0.f);
                    }
                }
            }
#pragma unroll
            for (int m = 0; m < 4; m++) {
                int c0 = 4 * (q + 4 * m);
                float4 aa = ((const float4*)g_a)[q + 4 * m];
                float4 bb = ((const float4*)g_bc)[q + 4 * m];
                G[(c0 + 0) * GSTRIDE + v] = aa.x * cen[m].x + bb.x;
                G[(c0 + 1) * GSTRIDE + v] = aa.y * cen[m].y + bb.y;
                G[(c0 + 2) * GSTRIDE + v] = aa.z * cen[m].z + bb.z;
                G[(c0 + 3) * GSTRIDE + v] = aa.w * cen[m].w + bb.w;
                G[(64 + c0 + 0) * GSTRIDE + v] = aa.x * sm[m].x + 6.f * bb.x;
                G[(64 + c0 + 1) * GSTRIDE + v] = aa.y * sm[m].y + 6.f * bb.y;
                G[(64 + c0 + 2) * GSTRIDE + v] = aa.z * sm[m].z + 6.f * bb.z;
                G[(64 + c0 + 3) * GSTRIDE + v] = aa.w * sm[m].w + 6.f * bb.w;
            }
        }
    }
    __syncthreads();

    int og = tid & 7, vg = tid >> 3;    // NEW mapping
    float av[4][8];
    gemm_core(G, Ws, vg, og, av);

    // residual + relu (coalesced: 8 og x 4 vertices -> 256B runs)
    int nq = n0 + 4 * vg;
    if (nq < N_) {
        const float4* h4 = (const float4*)g_h;
#pragma unroll
        for (int i = 0; i < 4; i++) {
            size_t row = (size_t)(rbase + nq + i) * 16 + og * 2;
            float4 r0 = h4[row], r1 = h4[row + 1];
            av[i][0] = fmaxf(av[i][0] + r0.x, 0.f);
            av[i][1] = fmaxf(av[i][1] + r0.y, 0.f);
            av[i][2] = fmaxf(av[i][2] + r0.z, 0.f);
            av[i][3] = fmaxf(av[i][3] + r0.w, 0.f);
            av[i][4] = fmaxf(av[i][4] + r1.x, 0.f);
            av[i][5] = fmaxf(av[i][5] + r1.y, 0.f);
            av[i][6] = fmaxf(av[i][6] + r1.z, 0.f);
            av[i][7] = fmaxf(av[i][7] + r1.w, 0.f);
        }
#pragma unroll
        for (int o = 0; o < 8; o++) {
            float4 v4 = make_float4(av[0][o], av[1][o], av[2][o], av[3][o]);
            *(float4*)(out + (size_t)(b * 64 + og * 8 + o) * N_ + nq) = v4;
        }
    }
}

// ---------------------------------------------------------------------------
extern "C" void kernel_launch(void* const* d_in, const int* in_sizes, int n_in,
                              void* d_out, int out_size) {
    const float* x     = (const float*)d_in[0];
    const int*   neigh = (const int*)d_in[1];
    const float* W0    = (const float*)d_in[2];
    const float* W1    = (const float*)d_in[3];
    const float* gamma = (const float*)d_in[4];
    const float* beta  = (const float*)d_in[5];
    float* out = (float*)d_out;

    cudaFuncSetAttribute(conv1_k, cudaFuncAttributeMaxDynamicSharedMemorySize, SMEM_BYTES);
    cudaFuncSetAttribute(conv2_k, cudaFuncAttributeMaxDynamicSharedMemorySize, SMEM_BYTES);

    dim3 gtr(N_ / 32, B_);
    dim3 gconv(NTILES, B_);
    prep_k<<<1, 256>>>(W0, W1);
    transpose_k<<<gtr, 256>>>(x);
    dummy_k<<<1, 32>>>();                  // keeps conv1 in the profiled slot
    conv1_k<<<gconv, 256, SMEM_BYTES>>>(neigh);
    finalize_k<<<1, 64>>>(gamma, beta);
    conv2_k<<<gconv, 256, SMEM_BYTES>>>(neigh, out);
}

// round 17
// speedup vs baseline: 2.8522x; 2.8522x over previous
#include <cuda_runtime.h>
#include <cstdint>

#define B_ 4
#define C_ 64
#define N_ 100000
#define K_ 6
#define BN_ (B_ * N_)
#define EPS_ 1e-5f
#define TILE_V 128
#define NTILES ((N_ + TILE_V - 1) / TILE_V)   // 782
#define GSTRIDE 132                           // padded G row stride (floats)
#define SMEM_BYTES (32768 + 128 * GSTRIDE * 4)  // Ws 32KB + G 66KB = 100352

// device scratch
__device__ float g_xt[(size_t)BN_ * 64];   // x transposed [B*N][64]
__device__ float g_h[(size_t)BN_ * 64];    // conv1 pre-relu output
__device__ float g_W0t[128 * 64];          // W permuted: row k <-> channel c(k)
__device__ float g_W1t[128 * 64];
__device__ float g_sum[64], g_ssq[64], g_a[64], g_bc[64];

__device__ __forceinline__ void ffma2(unsigned long long& d,
                                      unsigned long long a,
                                      unsigned long long b) {
    asm("fma.rn.f32x2 %0, %1, %2, %0;" : "+l"(d) : "l"(a), "l"(b));
}
__device__ __forceinline__ unsigned long long dup2(float g) {
    unsigned long long v;
    asm("mov.b64 %0, {%1, %1};" : "=l"(v) : "f"(g));
    return v;
}
__device__ __forceinline__ float2 u2f(unsigned long long v) {
    float2 f; asm("mov.b64 {%0,%1}, %2;" : "=f"(f.x), "=f"(f.y) : "l"(v)); return f;
}

// ---------------------------------------------------------------------------
// prep: zero stats; build PERMUTED weights. GEMM k-row kk (0..127):
//   k' = kk & 63; q = k'&7; t = k'>>3; m = t>>2; j = t&3
//   source channel c = 4*(q + 8*m) + j ; s = kk>>6 (0 center / 1 neighbor)
// ---------------------------------------------------------------------------
__global__ void prep_k(const float* __restrict__ W0, const float* __restrict__ W1) {
    int t = threadIdx.x;
    if (t < 64) { g_sum[t] = 0.f; g_ssq[t] = 0.f; }
    for (int d = t; d < 8192; d += 256) {
        int kk = d >> 6, o = d & 63;
        int kp = kk & 63, s = kk >> 6;
        int q = kp & 7, tt = kp >> 3;
        int m = tt >> 2, j = tt & 3;
        int c = 4 * (q + 8 * m) + j;
        int src = o * 128 + c * 2 + s;
        g_W0t[d] = W0[src];
        g_W1t[d] = W1[src];
    }
}

__global__ void dummy_k() {}

// ---------------------------------------------------------------------------
__global__ void transpose_k(const float* __restrict__ x) {
    __shared__ float tile[64][33];
    int b = blockIdx.y;
    int n0 = blockIdx.x * 32;
    const float* xb = x + (size_t)b * C_ * N_;
    int t = threadIdx.x;
#pragma unroll
    for (int i = 0; i < 8; i++) {
        int idx = t + i * 256;
        int c = idx >> 5, j = idx & 31;
        tile[c][j] = xb[(size_t)c * N_ + n0 + j];
    }
    __syncthreads();
    float* dst = g_xt + ((size_t)b * N_ + n0) * C_;
#pragma unroll
    for (int i = 0; i < 8; i++) {
        int idx = t + i * 256;
        int j = idx >> 6, c = idx & 63;
        dst[j * C_ + c] = tile[c][j];
    }
}

// ---------------------------------------------------------------------------
// GEMM (FROZEN R14 version): G [128 k][GSTRIDE], Ws [128 k][64 o];
// thread = 4 vertices (vg=lane) x 8 outputs (og=warp).
// ---------------------------------------------------------------------------
__device__ __forceinline__ void gemm_core(const float* __restrict__ G,
                                          const float* __restrict__ Ws,
                                          int vg, int og, float av[4][8]) {
    unsigned long long acc[4][4];
#pragma unroll
    for (int v = 0; v < 4; v++)
#pragma unroll
        for (int p = 0; p < 4; p++) acc[v][p] = 0ull;

    const float* Gp = G + 4 * vg;
    const float* Wp = Ws + og * 8;
#pragma unroll 16
    for (int k = 0; k < 128; k++) {
        float4 g4 = *(const float4*)(Gp + (size_t)k * GSTRIDE);
        ulonglong2 w01 = *(const ulonglong2*)(Wp + (size_t)k * 64);
        ulonglong2 w23 = *(const ulonglong2*)(Wp + (size_t)k * 64 + 4);
        unsigned long long gd0 = dup2(g4.x), gd1 = dup2(g4.y);
        unsigned long long gd2 = dup2(g4.z), gd3 = dup2(g4.w);
        ffma2(acc[0][0], gd0, w01.x); ffma2(acc[0][1], gd0, w01.y);
        ffma2(acc[0][2], gd0, w23.x); ffma2(acc[0][3], gd0, w23.y);
        ffma2(acc[1][0], gd1, w01.x); ffma2(acc[1][1], gd1, w01.y);
        ffma2(acc[1][2], gd1, w23.x); ffma2(acc[1][3], gd1, w23.y);
        ffma2(acc[2][0], gd2, w01.x); ffma2(acc[2][1], gd2, w01.y);
        ffma2(acc[2][2], gd2, w23.x); ffma2(acc[2][3], gd2, w23.y);
        ffma2(acc[3][0], gd3, w01.x); ffma2(acc[3][1], gd3, w01.y);
        ffma2(acc[3][2], gd3, w23.x); ffma2(acc[3][3], gd3, w23.y);
    }
#pragma unroll
    for (int v = 0; v < 4; v++)
#pragma unroll
        for (int p = 0; p < 4; p++) {
            float2 f = u2f(acc[v][p]);
            av[v][2 * p] = f.x;
            av[v][2 * p + 1] = f.y;
        }
}

// ---------------------------------------------------------------------------
// conv1: full-line gather (8 lanes/row, 4 passes of 32 vertices) -> permuted
// G rows (conflict-free STS); frozen GEMM; h store; relu stats.
// ---------------------------------------------------------------------------
__global__ __launch_bounds__(256, 2) void conv1_k(const int* __restrict__ neigh) {
    extern __shared__ float smem[];
    float* Ws = smem;            // [128][64] 32 KB
    float* G  = smem + 8192;     // [128][GSTRIDE]

    int tid = threadIdx.x;
    int b = blockIdx.y, n0 = blockIdx.x * TILE_V, rbase = b * N_;

    {   // stage weights
        const float4* src = (const float4*)g_W0t;
        float4* dst = (float4*)Ws;
        for (int i = tid; i < 2048; i += 256) dst[i] = src[i];
    }

    {   // gather: lane = (vs = tid>>3, q = tid&7); 4 passes of 32 vertices.
        // Each LDG instr: 4 rows x full 128B line -> 4 wavefronts.
        int q = tid & 7, vs = tid >> 3;
        const float4* xt4 = (const float4*)g_xt;
#pragma unroll
        for (int p = 0; p < 4; p++) {
            int v = p * 32 + vs;
            int n = n0 + v;
            bool ok = (n < N_);
            float4 cen[2], sm[2];
#pragma unroll
            for (int m = 0; m < 2; m++) {
                cen[m] = make_float4(0.f, 0.f, 0.f, 0.f);
                sm[m]  = make_float4(0.f, 0.f, 0.f, 0.f);
            }
            if (ok) {
                size_t vr = (size_t)(rbase + n) * 16 + q;
                cen[0] = xt4[vr];
                cen[1] = xt4[vr + 8];
                const int* nb = neigh + (size_t)(rbase + n) * K_;
                int idx[6] = {nb[0], nb[1], nb[2], nb[3], nb[4], nb[5]};
#pragma unroll
                for (int k = 0; k < 6; k++) {
                    size_t r = (size_t)(rbase + idx[k]) * 16 + q;
                    float4 a0 = xt4[r];
                    float4 a1 = xt4[r + 8];
                    sm[0].x += a0.x; sm[0].y += a0.y; sm[0].z += a0.z; sm[0].w += a0.w;
                    sm[1].x += a1.x; sm[1].y += a1.y; sm[1].z += a1.z; sm[1].w += a1.w;
                }
            }
            // permuted STS: component j of chunk m -> k-row q + 8*(4m+j)
#pragma unroll
            for (int m = 0; m < 2; m++) {
                float cc[4] = {cen[m].x, cen[m].y, cen[m].z, cen[m].w};
                float ssv[4] = {sm[m].x, sm[m].y, sm[m].z, sm[m].w};
#pragma unroll
                for (int j = 0; j < 4; j++) {
                    int kc = q + 8 * (4 * m + j);
                    G[kc * GSTRIDE + v] = cc[j];
                    G[(64 + kc) * GSTRIDE + v] = ssv[j];
                }
            }
        }
    }
    __syncthreads();

    int vg = tid & 31, og = tid >> 5;   // FROZEN R14 mapping
    float av[4][8];
    gemm_core(G, Ws, vg, og, av);

    float4* h4 = (float4*)g_h;
#pragma unroll
    for (int i = 0; i < 4; i++) {
        int n = n0 + 4 * vg + i;
        if (n < N_) {
            size_t row = (size_t)(rbase + n) * 16 + og * 2;
            h4[row]     = make_float4(av[i][0], av[i][1], av[i][2], av[i][3]);
            h4[row + 1] = make_float4(av[i][4], av[i][5], av[i][6], av[i][7]);
        }
    }

    // relu stats: warp og owns channels og*8..og*8+7
#pragma unroll
    for (int o = 0; o < 8; o++) {
        float s = 0.f, q2 = 0.f;
#pragma unroll
        for (int i = 0; i < 4; i++) {
            float r = fmaxf(av[i][o], 0.f);
            s += r; q2 += r * r;
        }
#pragma unroll
        for (int off = 16; off; off >>= 1) {
            s  += __shfl_xor_sync(0xffffffffu, s, off);
            q2 += __shfl_xor_sync(0xffffffffu, q2, off);
        }
        if (vg == 0) {
            atomicAdd(&g_sum[og * 8 + o], s);
            atomicAdd(&g_ssq[og * 8 + o], q2);
        }
    }
}

// ---------------------------------------------------------------------------
__global__ void finalize_k(const float* __restrict__ gamma, const float* __restrict__ beta) {
    int c = threadIdx.x;
    float inv = 1.f / (float)BN_;
    float mean = g_sum[c] * inv;
    float var = g_ssq[c] * inv - mean * mean;
    float a = gamma[c] * rsqrtf(var + EPS_);
    g_a[c] = a;
    g_bc[c] = beta[c] - mean * a;
}

// ---------------------------------------------------------------------------
// conv2: full-line gather with BN-affine fold; frozen GEMM; +residual; relu;
// transposed output stores.
// ---------------------------------------------------------------------------
__global__ __launch_bounds__(256, 2) void conv2_k(const int* __restrict__ neigh,
                                                  float* __restrict__ out) {
    extern __shared__ float smem[];
    float* Ws = smem;
    float* G  = smem + 8192;

    int tid = threadIdx.x;
    int b = blockIdx.y, n0 = blockIdx.x * TILE_V, rbase = b * N_;

    {
        const float4* src = (const float4*)g_W1t;
        float4* dst = (float4*)Ws;
        for (int i = tid; i < 2048; i += 256) dst[i] = src[i];
    }

    {   // gather: center a*relu(h)+b ; neighbors a*sum(relu(h_k)) + 6b
        int q = tid & 7, vs = tid >> 3;
        const float4* h4 = (const float4*)g_h;
        float4 aa0 = ((const float4*)g_a)[q],     bb0 = ((const float4*)g_bc)[q];
        float4 aa1 = ((const float4*)g_a)[q + 8], bb1 = ((const float4*)g_bc)[q + 8];
#pragma unroll
        for (int p = 0; p < 4; p++) {
            int v = p * 32 + vs;
            int n = n0 + v;
            bool ok = (n < N_);
            float4 cen[2], sm[2];
#pragma unroll
            for (int m = 0; m < 2; m++) {
                cen[m] = make_float4(0.f, 0.f, 0.f, 0.f);
                sm[m]  = make_float4(0.f, 0.f, 0.f, 0.f);
            }
            if (ok) {
                size_t vr = (size_t)(rbase + n) * 16 + q;
                float4 h0 = h4[vr], h1 = h4[vr + 8];
                cen[0].x = aa0.x * fmaxf(h0.x, 0.f) + bb0.x;
                cen[0].y = aa0.y * fmaxf(h0.y, 0.f) + bb0.y;
                cen[0].z = aa0.z * fmaxf(h0.z, 0.f) + bb0.z;
                cen[0].w = aa0.w * fmaxf(h0.w, 0.f) + bb0.w;
                cen[1].x = aa1.x * fmaxf(h1.x, 0.f) + bb1.x;
                cen[1].y = aa1.y * fmaxf(h1.y, 0.f) + bb1.y;
                cen[1].z = aa1.z * fmaxf(h1.z, 0.f) + bb1.z;
                cen[1].w = aa1.w * fmaxf(h1.w, 0.f) + bb1.w;
                const int* nb = neigh + (size_t)(rbase + n) * K_;
                int idx[6] = {nb[0], nb[1], nb[2], nb[3], nb[4], nb[5]};
#pragma unroll
                for (int k = 0; k < 6; k++) {
                    size_t r = (size_t)(rbase + idx[k]) * 16 + q;
                    float4 a0 = h4[r], a1 = h4[r + 8];
                    sm[0].x += fmaxf(a0.x, 0.f); sm[0].y += fmaxf(a0.y, 0.f);
                    sm[0].z += fmaxf(a0.z, 0.f); sm[0].w += fmaxf(a0.w, 0.f);
                    sm[1].x += fmaxf(a1.x, 0.f); sm[1].y += fmaxf(a1.y, 0.f);
                    sm[1].z += fmaxf(a1.z, 0.f); sm[1].w += fmaxf(a1.w, 0.f);
                }
                sm[0].x = aa0.x * sm[0].x + 6.f * bb0.x;
                sm[0].y = aa0.y * sm[0].y + 6.f * bb0.y;
                sm[0].z = aa0.z * sm[0].z + 6.f * bb0.z;
                sm[0].w = aa0.w * sm[0].w + 6.f * bb0.w;
                sm[1].x = aa1.x * sm[1].x + 6.f * bb1.x;
                sm[1].y = aa1.y * sm[1].y + 6.f * bb1.y;
                sm[1].z = aa1.z * sm[1].z + 6.f * bb1.z;
                sm[1].w = aa1.w * sm[1].w + 6.f * bb1.w;
            }
#pragma unroll
            for (int m = 0; m < 2; m++) {
                float cc[4] = {cen[m].x, cen[m].y, cen[m].z, cen[m].w};
                float ssv[4] = {sm[m].x, sm[m].y, sm[m].z, sm[m].w};
#pragma unroll
                for (int j = 0; j < 4; j++) {
                    int kc = q + 8 * (4 * m + j);
                    G[kc * GSTRIDE + v] = cc[j];
                    G[(64 + kc) * GSTRIDE + v] = ssv[j];
                }
            }
        }
    }
    __syncthreads();

    int vg = tid & 31, og = tid >> 5;   // FROZEN R14 mapping
    float av[4][8];
    gemm_core(G, Ws, vg, og, av);

    // residual + relu, then transposed float4 stores (4 consecutive vertices)
    int nq = n0 + 4 * vg;
    if (nq < N_) {
        const float4* h4 = (const float4*)g_h;
#pragma unroll
        for (int i = 0; i < 4; i++) {
            size_t row = (size_t)(rbase + nq + i) * 16 + og * 2;
            float4 r0 = h4[row], r1 = h4[row + 1];
            av[i][0] = fmaxf(av[i][0] + r0.x, 0.f);
            av[i][1] = fmaxf(av[i][1] + r0.y, 0.f);
            av[i][2] = fmaxf(av[i][2] + r0.z, 0.f);
            av[i][3] = fmaxf(av[i][3] + r0.w, 0.f);
            av[i][4] = fmaxf(av[i][4] + r1.x, 0.f);
            av[i][5] = fmaxf(av[i][5] + r1.y, 0.f);
            av[i][6] = fmaxf(av[i][6] + r1.z, 0.f);
            av[i][7] = fmaxf(av[i][7] + r1.w, 0.f);
        }
#pragma unroll
        for (int o = 0; o < 8; o++) {
            float4 v4 = make_float4(av[0][o], av[1][o], av[2][o], av[3][o]);
            *(float4*)(out + (size_t)(b * 64 + og * 8 + o) * N_ + nq) = v4;
        }
    }
}

// ---------------------------------------------------------------------------
extern "C" void kernel_launch(void* const* d_in, const int* in_sizes, int n_in,
                              void* d_out, int out_size) {
    const float* x     = (const float*)d_in[0];
    const int*   neigh = (const int*)d_in[1];
    const float* W0    = (const float*)d_in[2];
    const float* W1    = (const float*)d_in[3];
    const float* gamma = (const float*)d_in[4];
    const float* beta  = (const float*)d_in[5];
    float* out = (float*)d_out;

    cudaFuncSetAttribute(conv1_k, cudaFuncAttributeMaxDynamicSharedMemorySize, SMEM_BYTES);
    cudaFuncSetAttribute(conv2_k, cudaFuncAttributeMaxDynamicSharedMemorySize, SMEM_BYTES);

    dim3 gtr(N_ / 32, B_);
    dim3 gconv(NTILES, B_);
    prep_k<<<1, 256>>>(W0, W1);
    transpose_k<<<gtr, 256>>>(x);
    dummy_k<<<1, 32>>>();                  // keeps conv1 in the profiled slot
    conv1_k<<<gconv, 256, SMEM_BYTES>>>(neigh);
    finalize_k<<<1, 64>>>(gamma, beta);
    conv2_k<<<gconv, 256, SMEM_BYTES>>>(neigh, out);
}